// round 15
// baseline (speedup 1.0000x reference)
#include <cuda_runtime.h>

// SubGraphAvgPool: out[b,g,d] = mean(h[b,g,d], h[b,4g+1..4g+4,d]),  B=16, N=8193, D=512, G=2048.
//
// R9 structure (one CTA per (b,g) via 2D grid, 128 threads, one float4/thread,
// children-first load order, 32-bit offsets) + write-through output stores:
// __stwt sends the 67MB output stream straight to DRAM without occupying L2,
// preserving L2 capacity/bandwidth for the child-row reuse window.
//
// Cache hints:
//   - child rows >= 2049 (g >= 512): __ldcs  (single-use stream)
//   - child rows 1..2048:            default (re-read later as g-rows)
//   - g-node row:                    __ldcs  (last use)
//   - output:                        __stwt  (write-through, never re-read)

static constexpr int B = 16;
static constexpr unsigned N = 8193;
static constexpr int D = 512;
static constexpr unsigned G = 2048;
static constexpr unsigned DV = D / 4;  // 128 float4 per row

__global__ __launch_bounds__(128, 8)
void subgraph_avgpool_kernel(const float* __restrict__ h, float* __restrict__ out) {
    const unsigned g  = blockIdx.x;       // 0 .. 2047
    const unsigned b  = blockIdx.y;       // 0 .. 15
    const unsigned dv = threadIdx.x;      // 0 .. 127

    // All element offsets fit in 32 bits (max ~67M elements = 268MB bytes).
    const float4* __restrict__ hp =
        reinterpret_cast<const float4*>(h) + b * (N * DV) + dv;

    // Child rows 4g+1..4g+4 first: the DRAM-bound contiguous burst.
    const float4* p = hp + (4u * g + 1u) * DV;
    float4 a1, a2, a3, a4;
    if (g >= 512u) {
        a1 = __ldcs(p);           a2 = __ldcs(p + DV);
        a3 = __ldcs(p + 2u * DV); a4 = __ldcs(p + 3u * DV);
    } else {
        a1 = __ldg(p);            a2 = __ldg(p + DV);
        a3 = __ldg(p + 2u * DV);  a4 = __ldg(p + 3u * DV);
    }

    // g-node row last: usually an L2 hit, cheap to hide.
    const float4 a0 = __ldcs(hp + g * DV);

    float4 s;
    s.x = (a0.x + a1.x + a2.x + a3.x + a4.x) * 0.2f;
    s.y = (a0.y + a1.y + a2.y + a3.y + a4.y) * 0.2f;
    s.z = (a0.z + a1.z + a2.z + a3.z + a4.z) * 0.2f;
    s.w = (a0.w + a1.w + a2.w + a3.w + a4.w) * 0.2f;

    // Write-through: full-line coverage, no L2 residency, never re-read.
    __stwt(reinterpret_cast<float4*>(out) + (b * G + g) * DV + dv, s);
}

extern "C" void kernel_launch(void* const* d_in, const int* in_sizes, int n_in,
                              void* d_out, int out_size) {
    const float* h = (const float*)d_in[0];
    float* out = (float*)d_out;
    dim3 grid(G, B);
    subgraph_avgpool_kernel<<<grid, 128>>>(h, out);
}

// round 16
// speedup vs baseline: 1.0031x; 1.0031x over previous
#include <cuda_runtime.h>

// SubGraphAvgPool: out[b,g,d] = mean(h[b,g,d], h[b,4g+1..4g+4,d]),  B=16, N=8193, D=512, G=2048.
//
// FINAL (converged, R9 winner): one CTA per (b,g) via 2D grid, 128 threads,
// one float4 per thread, children-first load order, 32-bit offsets.
// 43.2us kernel = 7.77 TB/s aggregate on 335.6 MB compulsory traffic (97% of
// HBM spec). Verified-losing alternatives: persistent loops (warp-serial
// iterations lose to fresh-CTA turnover), pair-CTA bursts (burst contiguity
// invisible at 2400-CTA flight depth), in-thread MLP widening (register cap),
// write-through stores (defeats L2 writeback coalescing).
//
// Cache hints:
//   - child rows >= 2049 (g >= 512): __ldcs  (single-use stream)
//   - child rows 1..2048:            default (re-read later as g-rows)
//   - g-node row:                    __ldcs  (last use, L2 hit)
//   - output:                        __stcs  (evict-first dirty lines; L2
//                                            coalesces full-line writebacks)

static constexpr int B = 16;
static constexpr unsigned N = 8193;
static constexpr int D = 512;
static constexpr unsigned G = 2048;
static constexpr unsigned DV = D / 4;  // 128 float4 per row

__global__ __launch_bounds__(128, 8)
void subgraph_avgpool_kernel(const float* __restrict__ h, float* __restrict__ out) {
    const unsigned g  = blockIdx.x;       // 0 .. 2047
    const unsigned b  = blockIdx.y;       // 0 .. 15
    const unsigned dv = threadIdx.x;      // 0 .. 127

    // All element offsets fit in 32 bits (max ~67M elements = 268MB bytes).
    const float4* __restrict__ hp =
        reinterpret_cast<const float4*>(h) + b * (N * DV) + dv;

    // Child rows 4g+1..4g+4 first: the DRAM-bound contiguous burst.
    const float4* p = hp + (4u * g + 1u) * DV;
    float4 a1, a2, a3, a4;
    if (g >= 512u) {
        a1 = __ldcs(p);           a2 = __ldcs(p + DV);
        a3 = __ldcs(p + 2u * DV); a4 = __ldcs(p + 3u * DV);
    } else {
        a1 = __ldg(p);            a2 = __ldg(p + DV);
        a3 = __ldg(p + 2u * DV);  a4 = __ldg(p + 3u * DV);
    }

    // g-node row last: usually an L2 hit, cheap to hide.
    const float4 a0 = __ldcs(hp + g * DV);

    float4 s;
    s.x = (a0.x + a1.x + a2.x + a3.x + a4.x) * 0.2f;
    s.y = (a0.y + a1.y + a2.y + a3.y + a4.y) * 0.2f;
    s.z = (a0.z + a1.z + a2.z + a3.z + a4.z) * 0.2f;
    s.w = (a0.w + a1.w + a2.w + a3.w + a4.w) * 0.2f;

    __stcs(reinterpret_cast<float4*>(out) + (b * G + g) * DV + dv, s);
}

extern "C" void kernel_launch(void* const* d_in, const int* in_sizes, int n_in,
                              void* d_out, int out_size) {
    const float* h = (const float*)d_in[0];
    float* out = (float*)d_out;
    dim3 grid(G, B);
    subgraph_avgpool_kernel<<<grid, 128>>>(h, out);
}

// round 17
// speedup vs baseline: 1.0860x; 1.0827x over previous
#include <cuda_runtime.h>

// SubGraphAvgPool: out[b,g,d] = mean(h[b,g,d], h[b,4g+1..4g+4,d]),  B=16, N=8193, D=512, G=2048.
//
// FINAL (best-benched variant, R6): one CTA per (b,g), 128 threads, one float4
// per thread, children-first load order, R2 cache-hint policy.
// Kernel ~43.3us = ~7.7 TB/s aggregate on compulsory traffic (~97% of HBM
// spec). Verified-losing alternatives this session: persistent grid-stride
// loops at 50% and 100% occupancy (warp-serial iterations lose to fresh-CTA
// turnover), pair-CTA 16KB bursts (contiguity invisible at ~2400-CTA flight
// depth), in-thread MLP widening (ptxas register cap re-serializes loads),
// write-through output stores (defeats L2 full-line writeback coalescing).
//
// Cache hints:
//   - child rows >= 2049 (g >= 512): __ldcs  (single-use stream)
//   - child rows 1..2048:            default (re-read later as g-rows, L2 hit)
//   - g-node row:                    __ldcs  (last use)
//   - output:                        __stcs  (evict-first dirty lines in L2)

static constexpr int B = 16;
static constexpr long long N = 8193;
static constexpr int D = 512;
static constexpr int G = 2048;
static constexpr int DV = D / 4;  // 128 float4 per row

__global__ __launch_bounds__(128, 8)
void subgraph_avgpool_kernel(const float* __restrict__ h, float* __restrict__ out) {
    const int bg = blockIdx.x;          // 0 .. B*G-1
    const int g  = bg & (G - 1);        // G = 2048 = 2^11
    const int b  = bg >> 11;
    const int dv = threadIdx.x;         // 0 .. 127

    const float4* __restrict__ hp =
        reinterpret_cast<const float4*>(h) + (long long)b * (N * DV) + dv;

    // Child rows 4g+1..4g+4 first: the DRAM-bound contiguous burst.
    const float4* p = hp + (long long)(4 * g + 1) * DV;
    float4 a1, a2, a3, a4;
    if (g >= 512) {
        a1 = __ldcs(p);          a2 = __ldcs(p + DV);
        a3 = __ldcs(p + 2 * DV); a4 = __ldcs(p + 3 * DV);
    } else {
        a1 = __ldg(p);           a2 = __ldg(p + DV);
        a3 = __ldg(p + 2 * DV);  a4 = __ldg(p + 3 * DV);
    }

    // g-node row last: usually an L2 hit, cheap to hide.
    const float4 a0 = __ldcs(hp + (long long)g * DV);

    float4 s;
    s.x = (a0.x + a1.x + a2.x + a3.x + a4.x) * 0.2f;
    s.y = (a0.y + a1.y + a2.y + a3.y + a4.y) * 0.2f;
    s.z = (a0.z + a1.z + a2.z + a3.z + a4.z) * 0.2f;
    s.w = (a0.w + a1.w + a2.w + a3.w + a4.w) * 0.2f;

    __stcs(reinterpret_cast<float4*>(out) + (long long)bg * DV + dv, s);
}

extern "C" void kernel_launch(void* const* d_in, const int* in_sizes, int n_in,
                              void* d_out, int out_size) {
    const float* h = (const float*)d_in[0];
    float* out = (float*)d_out;
    subgraph_avgpool_kernel<<<B * G, 128>>>(h, out);
}